// round 3
// baseline (speedup 1.0000x reference)
#include <cuda_runtime.h>
#include <math.h>

#define T_TOK 4096
#define HDIM  1024
#define IDIM  1408
#define NEXP  8
#define NPAIR (T_TOK * 2)          // 8192, exact (top-2, every token)
#define N2I   (2 * IDIM)           // 2816: gate||up concatenated
#define BM 64
#define BN 64
#define BK 16
#define MAXTILES 144               // <= 8192/64 + 8

// ---------------- scratch (static device globals; no allocations) ----------
__device__ int   g_count[NEXP];
__device__ int   g_list [NEXP * T_TOK];
__device__ float g_wt   [NEXP * T_TOK];
__device__ int   g_slot [NEXP * T_TOK];
__device__ int   g_base [NEXP];
__device__ int   g_tileE[MAXTILES];
__device__ int   g_tileRow[MAXTILES];
__device__ int   g_numTiles;
__device__ float g_P[(size_t)NPAIR * N2I];    // gate|up pre-activation
__device__ float g_h[(size_t)NPAIR * IDIM];   // silu(g)*u
__device__ float g_y[(size_t)NPAIR * HDIM];   // per-pair weighted output

// ---------------- init --------------------------------------------------
__global__ void k_init() {
    if (threadIdx.x < NEXP) g_count[threadIdx.x] = 0;
}

// ---------------- router: one warp per token ----------------------------
__global__ void k_router(const float* __restrict__ x, const float* __restrict__ rw) {
    int warp = (blockIdx.x * blockDim.x + threadIdx.x) >> 5;
    int lane = threadIdx.x & 31;
    if (warp >= T_TOK) return;
    const float* xr = x + (size_t)warp * HDIM;

    float xv[32];
#pragma unroll
    for (int j = 0; j < 32; j++) xv[j] = xr[lane + j * 32];

    float logits[NEXP];
#pragma unroll
    for (int e = 0; e < NEXP; e++) {
        const float* wr = rw + (size_t)e * HDIM;
        float acc = 0.f;
#pragma unroll
        for (int j = 0; j < 32; j++) acc += xv[j] * wr[lane + j * 32];
#pragma unroll
        for (int s = 16; s > 0; s >>= 1) acc += __shfl_xor_sync(0xffffffffu, acc, s);
        logits[e] = acc;
    }

    if (lane == 0) {
        int e1 = 0;
#pragma unroll
        for (int e = 1; e < NEXP; e++) if (logits[e] > logits[e1]) e1 = e;
        int e2 = (e1 == 0) ? 1 : 0;
#pragma unroll
        for (int e = 0; e < NEXP; e++)
            if (e != e1 && logits[e] > logits[e2]) e2 = e;
        float t  = expf(logits[e2] - logits[e1]);   // <= 1
        float w1 = 1.f / (1.f + t);
        float w2 = t   / (1.f + t);

        int i1 = atomicAdd(&g_count[e1], 1);
        g_list[e1 * T_TOK + i1] = warp;
        g_wt  [e1 * T_TOK + i1] = w1;
        g_slot[e1 * T_TOK + i1] = 2 * warp + 0;

        int i2 = atomicAdd(&g_count[e2], 1);
        g_list[e2 * T_TOK + i2] = warp;
        g_wt  [e2 * T_TOK + i2] = w2;
        g_slot[e2 * T_TOK + i2] = 2 * warp + 1;
    }
}

// ---------------- tile table --------------------------------------------
__global__ void k_build() {
    if (threadIdx.x != 0 || blockIdx.x != 0) return;
    int base = 0, nt = 0;
    for (int e = 0; e < NEXP; e++) {
        g_base[e] = base;
        int c = g_count[e];
        int tiles = (c + BM - 1) / BM;
        for (int r = 0; r < tiles; r++) {
            g_tileE[nt]   = e;
            g_tileRow[nt] = r * BM;
            nt++;
        }
        base += c;
    }
    g_numTiles = nt;
}

// ---------------- GEMM1: P[p, 0:2816] = x_gathered @ [Wg;Wu]^T ----------
__global__ void __launch_bounds__(256) k_gemm1(const float* __restrict__ x,
                                               const float* __restrict__ wg,
                                               const float* __restrict__ wu) {
    int tileIdx = blockIdx.y;
    if (tileIdx >= g_numTiles) return;
    int e    = g_tileE[tileIdx];
    int row0 = g_tileRow[tileIdx];
    int cnt  = g_count[e];
    int base = g_base[e];
    int n0   = blockIdx.x * BN;

    __shared__ float As[BK][BM];
    __shared__ float Bs[BK][BN];

    int tid     = threadIdx.x;
    int loadRow = tid >> 2;
    int loadVec = (tid & 3) * 4;
    int tx = tid & 15, ty = tid >> 4;

    int r = row0 + loadRow;
    const float* arow = (r < cnt) ? (x + (size_t)g_list[e * T_TOK + r] * HDIM) : nullptr;
    int nIdx = n0 + loadRow;
    const float* brow = (nIdx < IDIM)
        ? (wg + ((size_t)e * IDIM + nIdx) * HDIM)
        : (wu + ((size_t)e * IDIM + (nIdx - IDIM)) * HDIM);

    float acc[4][4] = {};

    for (int k0 = 0; k0 < HDIM; k0 += BK) {
        float4 av = arow ? *(const float4*)(arow + k0 + loadVec) : make_float4(0, 0, 0, 0);
        float4 bv = *(const float4*)(brow + k0 + loadVec);
        __syncthreads();
        As[loadVec + 0][loadRow] = av.x; As[loadVec + 1][loadRow] = av.y;
        As[loadVec + 2][loadRow] = av.z; As[loadVec + 3][loadRow] = av.w;
        Bs[loadVec + 0][loadRow] = bv.x; Bs[loadVec + 1][loadRow] = bv.y;
        Bs[loadVec + 2][loadRow] = bv.z; Bs[loadVec + 3][loadRow] = bv.w;
        __syncthreads();
#pragma unroll
        for (int kk = 0; kk < BK; kk++) {
            float a[4], b[4];
            *(float4*)a = *(const float4*)&As[kk][ty * 4];
            *(float4*)b = *(const float4*)&Bs[kk][tx * 4];
#pragma unroll
            for (int i = 0; i < 4; i++)
#pragma unroll
                for (int j = 0; j < 4; j++) acc[i][j] += a[i] * b[j];
        }
    }

#pragma unroll
    for (int i = 0; i < 4; i++) {
        int r2 = row0 + ty * 4 + i;
        if (r2 < cnt) {
            float4 v = make_float4(acc[i][0], acc[i][1], acc[i][2], acc[i][3]);
            *(float4*)&g_P[(size_t)(base + r2) * N2I + n0 + tx * 4] = v;
        }
    }
}

// ---------------- activation: h = silu(g) * u ---------------------------
__global__ void k_act() {
    size_t idx = (size_t)blockIdx.x * blockDim.x + threadIdx.x; // float4 index
    size_t total = (size_t)NPAIR * IDIM / 4;
    if (idx >= total) return;
    size_t p = idx / (IDIM / 4);
    size_t c = idx % (IDIM / 4);
    const float4 g4 = *(const float4*)&g_P[p * N2I + c * 4];
    const float4 u4 = *(const float4*)&g_P[p * N2I + IDIM + c * 4];
    float4 h4;
    h4.x = g4.x / (1.f + expf(-g4.x)) * u4.x;
    h4.y = g4.y / (1.f + expf(-g4.y)) * u4.y;
    h4.z = g4.z / (1.f + expf(-g4.z)) * u4.z;
    h4.w = g4.w / (1.f + expf(-g4.w)) * u4.w;
    *(float4*)&g_h[p * IDIM + c * 4] = h4;
}

// ---------------- GEMM2: y[slot] = wt * (h @ Wd^T) ----------------------
__global__ void __launch_bounds__(256) k_gemm2(const float* __restrict__ wd) {
    int tileIdx = blockIdx.y;
    if (tileIdx >= g_numTiles) return;
    int e    = g_tileE[tileIdx];
    int row0 = g_tileRow[tileIdx];
    int cnt  = g_count[e];
    int base = g_base[e];
    int n0   = blockIdx.x * BN;

    __shared__ float As[BK][BM];
    __shared__ float Bs[BK][BN];

    int tid     = threadIdx.x;
    int loadRow = tid >> 2;
    int loadVec = (tid & 3) * 4;
    int tx = tid & 15, ty = tid >> 4;

    int r = row0 + loadRow;
    const float* arow = (r < cnt) ? (g_h + (size_t)(base + r) * IDIM) : nullptr;
    int nIdx = n0 + loadRow;
    const float* brow = wd + ((size_t)e * HDIM + nIdx) * IDIM;

    float acc[4][4] = {};

    for (int k0 = 0; k0 < IDIM; k0 += BK) {
        float4 av = arow ? *(const float4*)(arow + k0 + loadVec) : make_float4(0, 0, 0, 0);
        float4 bv = *(const float4*)(brow + k0 + loadVec);
        __syncthreads();
        As[loadVec + 0][loadRow] = av.x; As[loadVec + 1][loadRow] = av.y;
        As[loadVec + 2][loadRow] = av.z; As[loadVec + 3][loadRow] = av.w;
        Bs[loadVec + 0][loadRow] = bv.x; Bs[loadVec + 1][loadRow] = bv.y;
        Bs[loadVec + 2][loadRow] = bv.z; Bs[loadVec + 3][loadRow] = bv.w;
        __syncthreads();
#pragma unroll
        for (int kk = 0; kk < BK; kk++) {
            float a[4], b[4];
            *(float4*)a = *(const float4*)&As[kk][ty * 4];
            *(float4*)b = *(const float4*)&Bs[kk][tx * 4];
#pragma unroll
            for (int i = 0; i < 4; i++)
#pragma unroll
                for (int j = 0; j < 4; j++) acc[i][j] += a[i] * b[j];
        }
    }

#pragma unroll
    for (int i = 0; i < 4; i++) {
        int r2 = row0 + ty * 4 + i;
        if (r2 < cnt) {
            float w  = g_wt  [e * T_TOK + r2];
            int slot = g_slot[e * T_TOK + r2];
            float4 v = make_float4(acc[i][0] * w, acc[i][1] * w,
                                   acc[i][2] * w, acc[i][3] * w);
            *(float4*)&g_y[(size_t)slot * HDIM + n0 + tx * 4] = v;
        }
    }
}

// ---------------- reduce: out[t] = y[2t] + y[2t+1] ----------------------
__global__ void k_reduce(float* __restrict__ out) {
    size_t idx = (size_t)blockIdx.x * blockDim.x + threadIdx.x; // float4 index
    size_t total = (size_t)T_TOK * HDIM / 4;
    if (idx >= total) return;
    size_t t = idx / (HDIM / 4);
    size_t c = idx % (HDIM / 4);
    const float4 a = *(const float4*)&g_y[(2 * t)     * HDIM + c * 4];
    const float4 b = *(const float4*)&g_y[(2 * t + 1) * HDIM + c * 4];
    float4 o = make_float4(a.x + b.x, a.y + b.y, a.z + b.z, a.w + b.w);
    *(float4*)&out[idx * 4] = o;
}

// ---------------- launch -------------------------------------------------
extern "C" void kernel_launch(void* const* d_in, const int* in_sizes, int n_in,
                              void* d_out, int out_size) {
    const float* x  = (const float*)d_in[0];  // [2,2048,1024]
    const float* rw = (const float*)d_in[1];  // [8,1024]
    const float* wg = (const float*)d_in[2];  // [8,1408,1024]
    const float* wu = (const float*)d_in[3];  // [8,1408,1024]
    const float* wd = (const float*)d_in[4];  // [8,1024,1408]
    float* out = (float*)d_out;

    k_init<<<1, 32>>>();
    k_router<<<T_TOK / 8, 256>>>(x, rw);          // 8 warps/block
    k_build<<<1, 1>>>();

    dim3 g1(N2I / BN, MAXTILES);                  // (44, 144)
    k_gemm1<<<g1, 256>>>(x, wg, wu);

    size_t actN = (size_t)NPAIR * IDIM / 4;
    k_act<<<(unsigned)((actN + 255) / 256), 256>>>();

    dim3 g2(HDIM / BN, MAXTILES);                 // (16, 144)
    k_gemm2<<<g2, 256>>>(wd);

    size_t redN = (size_t)T_TOK * HDIM / 4;
    k_reduce<<<(unsigned)((redN + 255) / 256), 256>>>(out);
}

// round 5
// speedup vs baseline: 2.4510x; 2.4510x over previous
#include <cuda_runtime.h>
#include <cuda_fp16.h>
#include <math.h>
#include <stdint.h>

#define T_TOK 4096
#define HDIM  1024
#define IDIM  1408
#define NEXP  8
#define NPAIR (T_TOK * 2)
#define N2I   (2 * IDIM)           // 2816
#define BM 128
#define BN 128
#define BKH 32                     // K halves per stage
#define MAXT 72                    // max M-tiles (BM=128)

// smem: rows padded to 80B (40 halves) for conflict-free ldmatrix
#define ROWB 80
#define REG  (128 * ROWB)          // 10240 B per operand region
#define O_AH 0
#define O_AL (REG)
#define O_BH (2 * REG)
#define O_BL (3 * REG)
#define STAGEB (4 * REG)           // 40960
#define SMEM_TOTAL (2 * STAGEB)    // 81920

// ---------------- scratch (static device globals; no allocations) ----------
__device__ int   g_count[NEXP];
__device__ int   g_list [NEXP * T_TOK];
__device__ float g_wt   [NEXP * T_TOK];
__device__ int   g_slot [NEXP * T_TOK];
__device__ int   g_base [NEXP];
__device__ int   g_tileE[MAXT];
__device__ int   g_tileRow[MAXT];
__device__ int   g_numTiles;

__device__ __half g_xh[(size_t)NPAIR * HDIM];
__device__ __half g_xl[(size_t)NPAIR * HDIM];
__device__ __half g_w1h[(size_t)NEXP * N2I * HDIM];   // gate||up, [E][2816][1024]
__device__ __half g_w1l[(size_t)NEXP * N2I * HDIM];
__device__ __half g_wdh[(size_t)NEXP * HDIM * IDIM];  // [E][1024][1408]
__device__ __half g_wdl[(size_t)NEXP * HDIM * IDIM];
__device__ __half g_hh[(size_t)NPAIR * IDIM];
__device__ __half g_hl[(size_t)NPAIR * IDIM];
__device__ float  g_P[(size_t)NPAIR * N2I];
__device__ float  g_y[(size_t)NPAIR * HDIM];

// ---------------- helpers -------------------------------------------------
__device__ __forceinline__ uint32_t smem_u32(const void* p) {
    uint32_t a;
    asm("{ .reg .u64 t; cvta.to.shared.u64 t, %1; cvt.u32.u64 %0, t; }" : "=r"(a) : "l"(p));
    return a;
}
__device__ __forceinline__ void cp16(uint32_t s, const void* g, bool v) {
    int sz = v ? 16 : 0;
    asm volatile("cp.async.cg.shared.global [%0], [%1], 16, %2;" :: "r"(s), "l"(g), "r"(sz) : "memory");
}
__device__ __forceinline__ void ldsm4(uint32_t* r, uint32_t addr) {
    asm volatile("ldmatrix.sync.aligned.m8n8.x4.shared.b16 {%0,%1,%2,%3}, [%4];"
                 : "=r"(r[0]), "=r"(r[1]), "=r"(r[2]), "=r"(r[3]) : "r"(addr));
}
__device__ __forceinline__ void mma16816(float* c, const uint32_t* a, uint32_t b0, uint32_t b1) {
    asm volatile("mma.sync.aligned.m16n8k16.row.col.f32.f16.f16.f32 "
                 "{%0,%1,%2,%3}, {%4,%5,%6,%7}, {%8,%9}, {%0,%1,%2,%3};"
                 : "+f"(c[0]), "+f"(c[1]), "+f"(c[2]), "+f"(c[3])
                 : "r"(a[0]), "r"(a[1]), "r"(a[2]), "r"(a[3]), "r"(b0), "r"(b1));
}
__device__ __forceinline__ void split_store(float4 v, __half* hp, __half* lp) {
    __half h0 = __float2half_rn(v.x), h1 = __float2half_rn(v.y);
    __half h2 = __float2half_rn(v.z), h3 = __float2half_rn(v.w);
    __half l0 = __float2half_rn(v.x - __half2float(h0));
    __half l1 = __float2half_rn(v.y - __half2float(h1));
    __half l2 = __float2half_rn(v.z - __half2float(h2));
    __half l3 = __float2half_rn(v.w - __half2float(h3));
    ((__half2*)hp)[0] = __halves2half2(h0, h1);
    ((__half2*)hp)[1] = __halves2half2(h2, h3);
    ((__half2*)lp)[0] = __halves2half2(l0, l1);
    ((__half2*)lp)[1] = __halves2half2(l2, l3);
}

// ---------------- init ----------------------------------------------------
__global__ void k_init() {
    if (threadIdx.x < NEXP) g_count[threadIdx.x] = 0;
}

// ---------------- router: one warp per token ------------------------------
__global__ void k_router(const float* __restrict__ x, const float* __restrict__ rw) {
    int warp = (blockIdx.x * blockDim.x + threadIdx.x) >> 5;
    int lane = threadIdx.x & 31;
    if (warp >= T_TOK) return;
    const float* xr = x + (size_t)warp * HDIM;

    float xv[32];
#pragma unroll
    for (int j = 0; j < 32; j++) xv[j] = xr[lane + j * 32];

    float logits[NEXP];
#pragma unroll
    for (int e = 0; e < NEXP; e++) {
        const float* wr = rw + (size_t)e * HDIM;
        float acc = 0.f;
#pragma unroll
        for (int j = 0; j < 32; j++) acc += xv[j] * wr[lane + j * 32];
#pragma unroll
        for (int s = 16; s > 0; s >>= 1) acc += __shfl_xor_sync(0xffffffffu, acc, s);
        logits[e] = acc;
    }

    if (lane == 0) {
        int e1 = 0;
#pragma unroll
        for (int e = 1; e < NEXP; e++) if (logits[e] > logits[e1]) e1 = e;
        int e2 = (e1 == 0) ? 1 : 0;
#pragma unroll
        for (int e = 0; e < NEXP; e++)
            if (e != e1 && logits[e] > logits[e2]) e2 = e;
        float t  = expf(logits[e2] - logits[e1]);
        float w1 = 1.f / (1.f + t);
        float w2 = t   / (1.f + t);

        int i1 = atomicAdd(&g_count[e1], 1);
        g_list[e1 * T_TOK + i1] = warp;
        g_wt  [e1 * T_TOK + i1] = w1;
        g_slot[e1 * T_TOK + i1] = 2 * warp + 0;

        int i2 = atomicAdd(&g_count[e2], 1);
        g_list[e2 * T_TOK + i2] = warp;
        g_wt  [e2 * T_TOK + i2] = w2;
        g_slot[e2 * T_TOK + i2] = 2 * warp + 1;
    }
}

// ---------------- tile table ---------------------------------------------
__global__ void k_build() {
    if (threadIdx.x != 0 || blockIdx.x != 0) return;
    int base = 0, nt = 0;
    for (int e = 0; e < NEXP; e++) {
        g_base[e] = base;
        int c = g_count[e];
        int tiles = (c + BM - 1) / BM;
        for (int r = 0; r < tiles; r++) {
            g_tileE[nt]   = e;
            g_tileRow[nt] = r * BM;
            nt++;
        }
        base += c;
    }
    g_numTiles = nt;
}

// ---------------- weight split: fp32 -> (hi,lo) halves -------------------
__global__ void k_splitw(const float* __restrict__ wg, const float* __restrict__ wu,
                         const float* __restrict__ wd) {
    const size_t W1 = (size_t)NEXP * N2I * HDIM;
    const size_t WD = (size_t)NEXP * HDIM * IDIM;
    size_t idx4 = (size_t)blockIdx.x * blockDim.x + threadIdx.x;
    if (idx4 < W1 / 4) {
        size_t f = idx4 * 4;
        size_t e = f / ((size_t)N2I * HDIM);
        size_t r = f % ((size_t)N2I * HDIM);
        size_t n = r / HDIM;
        size_t k = r % HDIM;
        const float* src = (n < IDIM) ? (wg + ((size_t)e * IDIM + n) * HDIM + k)
                                      : (wu + ((size_t)e * IDIM + (n - IDIM)) * HDIM + k);
        float4 v = *(const float4*)src;
        split_store(v, g_w1h + f, g_w1l + f);
    } else if (idx4 < (W1 + WD) / 4) {
        size_t f = (idx4 - W1 / 4) * 4;
        float4 v = *(const float4*)(wd + f);
        split_store(v, g_wdh + f, g_wdl + f);
    }
}

// ---------------- gather + split A rows into sorted order ----------------
__global__ void k_gather(const float* __restrict__ x) {
    int p = blockIdx.x;
    int e = 0;
#pragma unroll
    for (int i = 0; i < NEXP; i++)
        if (p >= g_base[i] && p < g_base[i] + g_count[i]) e = i;
    int r   = p - g_base[e];
    int tok = g_list[e * T_TOK + r];
    const float* src = x + (size_t)tok * HDIM;
    for (int c = threadIdx.x * 4; c < HDIM; c += blockDim.x * 4) {
        float4 v = *(const float4*)(src + c);
        split_store(v, g_xh + (size_t)p * HDIM + c, g_xl + (size_t)p * HDIM + c);
    }
}

// ---------------- split-fp16 HMMA GEMM -----------------------------------
// C[128,128] += A(hi+lo)[128,K] @ B(hi+lo)[128,K]^T   (3-term split)
template <int KD, bool G2>
__global__ void __launch_bounds__(256, 1) k_gemm() {
    int tileIdx = blockIdx.y;
    if (tileIdx >= g_numTiles) return;
    extern __shared__ char smem[];
    uint32_t sb = smem_u32(smem);
    int tid  = threadIdx.x;
    int lane = tid & 31, wid = tid >> 5;
    int wm0 = (wid >> 1) * 32;       // warp row origin (4 warps down)
    int wn0 = (wid & 1) * 64;        // warp col origin (2 warps across)

    int e = g_tileE[tileIdx], row0 = g_tileRow[tileIdx];
    int cnt = g_count[e], base = g_base[e];
    int n0 = blockIdx.x * BN;
    int mrem = cnt - row0;

    const __half* aH = (G2 ? g_hh : g_xh) + (size_t)(base + row0) * KD;
    const __half* aL = (G2 ? g_hl : g_xl) + (size_t)(base + row0) * KD;
    const int brows = G2 ? HDIM : N2I;
    const __half* bH = (G2 ? g_wdh : g_w1h) + ((size_t)e * brows + n0) * KD;
    const __half* bL = (G2 ? g_wdl : g_w1l) + ((size_t)e * brows + n0) * KD;

    // per-thread load slots: 512 16B-chunks per region, 2 per thread
    auto load_stage = [&](int buf, int k0) {
        uint32_t s0 = sb + buf * STAGEB;
#pragma unroll
        for (int i = 0; i < 2; i++) {
            int q = tid + i * 256;
            int row = q >> 2, c = q & 3;
            uint32_t so = row * ROWB + c * 16;
            size_t go = (size_t)row * KD + k0 + c * 8;   // halves
            bool v = row < mrem;
            cp16(s0 + O_AH + so, aH + go, v);
            cp16(s0 + O_AL + so, aL + go, v);
            cp16(s0 + O_BH + so, bH + go, true);
            cp16(s0 + O_BL + so, bL + go, true);
        }
        asm volatile("cp.async.commit_group;" ::: "memory");
    };

    float acc[2][8][4];
#pragma unroll
    for (int a = 0; a < 2; a++)
#pragma unroll
        for (int b = 0; b < 8; b++)
#pragma unroll
            for (int c = 0; c < 4; c++) acc[a][b][c] = 0.f;

    // ldmatrix lane addressing (within a 16-row x k16 block)
    int lr   = lane & 7;
    int lt   = lane >> 3;
    int rowoff  = lr + (lt & 1) * 8;
    int bytesel = (lt >> 1) * 16;

    const int STAGES = KD / BKH;
    load_stage(0, 0);
    for (int s = 0; s < STAGES; s++) {
        if (s + 1 < STAGES) {
            load_stage((s + 1) & 1, (s + 1) * BKH);
            asm volatile("cp.async.wait_group 1;" ::: "memory");
        } else {
            asm volatile("cp.async.wait_group 0;" ::: "memory");
        }
        __syncthreads();

        uint32_t s0 = sb + (s & 1) * STAGEB;
#pragma unroll
        for (int ks = 0; ks < 2; ks++) {
            uint32_t kb = ks * 32 + bytesel;
            uint32_t ah[2][4], al[2][4];
#pragma unroll
            for (int mt = 0; mt < 2; mt++) {
                uint32_t ra = (wm0 + mt * 16 + rowoff) * ROWB + kb;
                ldsm4(ah[mt], s0 + O_AH + ra);
                ldsm4(al[mt], s0 + O_AL + ra);
            }
#pragma unroll
            for (int ng = 0; ng < 4; ng++) {
                uint32_t rb = (wn0 + ng * 16 + rowoff) * ROWB + kb;
                uint32_t bh[4], bl[4];
                ldsm4(bh, s0 + O_BH + rb);
                ldsm4(bl, s0 + O_BL + rb);
#pragma unroll
                for (int mt = 0; mt < 2; mt++) {
                    float* c0 = acc[mt][ng * 2];
                    float* c1 = acc[mt][ng * 2 + 1];
                    mma16816(c0, ah[mt], bh[0], bh[2]);
                    mma16816(c1, ah[mt], bh[1], bh[3]);
                    mma16816(c0, ah[mt], bl[0], bl[2]);
                    mma16816(c1, ah[mt], bl[1], bl[3]);
                    mma16816(c0, al[mt], bh[0], bh[2]);
                    mma16816(c1, al[mt], bh[1], bh[3]);
                }
            }
        }
        __syncthreads();
    }

    // epilogue
    int gcol = n0 + wn0 + (lane & 3) * 2;
#pragma unroll
    for (int mt = 0; mt < 2; mt++) {
#pragma unroll
        for (int half = 0; half < 2; half++) {
            int rloc = wm0 + mt * 16 + (lane >> 2) + half * 8;
            if (rloc >= mrem) continue;
            int gr = row0 + rloc;
            float wscale;
            size_t dstbase;
            if (G2) {
                wscale  = g_wt[e * T_TOK + gr];
                dstbase = (size_t)g_slot[e * T_TOK + gr] * HDIM + gcol;
            } else {
                wscale  = 1.f;
                dstbase = (size_t)(base + gr) * N2I + gcol;
            }
            float* outp = (G2 ? g_y : g_P) + dstbase;
#pragma unroll
            for (int nt = 0; nt < 8; nt++) {
                float2 v;
                v.x = acc[mt][nt][half * 2 + 0] * wscale;
                v.y = acc[mt][nt][half * 2 + 1] * wscale;
                *(float2*)(outp + nt * 8) = v;
            }
        }
    }
}

// ---------------- activation: h = silu(g)*u -> (hi,lo) halves -------------
__global__ void k_act() {
    size_t idx = (size_t)blockIdx.x * blockDim.x + threadIdx.x;
    size_t tot = (size_t)NPAIR * IDIM / 4;
    if (idx >= tot) return;
    size_t p  = idx / (IDIM / 4);
    size_t c4 = idx % (IDIM / 4);
    float4 gg = *(const float4*)&g_P[p * N2I + c4 * 4];
    float4 uu = *(const float4*)&g_P[p * N2I + IDIM + c4 * 4];
    float4 h;
    h.x = gg.x / (1.f + expf(-gg.x)) * uu.x;
    h.y = gg.y / (1.f + expf(-gg.y)) * uu.y;
    h.z = gg.z / (1.f + expf(-gg.z)) * uu.z;
    h.w = gg.w / (1.f + expf(-gg.w)) * uu.w;
    split_store(h, g_hh + p * IDIM + c4 * 4, g_hl + p * IDIM + c4 * 4);
}

// ---------------- reduce: out[t] = y[2t] + y[2t+1] ------------------------
__global__ void k_reduce(float* __restrict__ out) {
    size_t idx = (size_t)blockIdx.x * blockDim.x + threadIdx.x;
    size_t total = (size_t)T_TOK * HDIM / 4;
    if (idx >= total) return;
    size_t t = idx / (HDIM / 4);
    size_t c = idx % (HDIM / 4);
    const float4 a = *(const float4*)&g_y[(2 * t)     * HDIM + c * 4];
    const float4 b = *(const float4*)&g_y[(2 * t + 1) * HDIM + c * 4];
    float4 o = make_float4(a.x + b.x, a.y + b.y, a.z + b.z, a.w + b.w);
    *(float4*)&out[idx * 4] = o;
}

// ---------------- launch --------------------------------------------------
extern "C" void kernel_launch(void* const* d_in, const int* in_sizes, int n_in,
                              void* d_out, int out_size) {
    const float* x  = (const float*)d_in[0];
    const float* rw = (const float*)d_in[1];
    const float* wg = (const float*)d_in[2];
    const float* wu = (const float*)d_in[3];
    const float* wd = (const float*)d_in[4];
    float* out = (float*)d_out;

    cudaFuncSetAttribute(k_gemm<HDIM, false>,
                         cudaFuncAttributeMaxDynamicSharedMemorySize, SMEM_TOTAL);
    cudaFuncSetAttribute(k_gemm<IDIM, true>,
                         cudaFuncAttributeMaxDynamicSharedMemorySize, SMEM_TOTAL);

    k_init<<<1, 32>>>();
    k_router<<<T_TOK / 8, 256>>>(x, rw);
    k_build<<<1, 1>>>();

    const size_t W1 = (size_t)NEXP * N2I * HDIM;
    const size_t WD = (size_t)NEXP * HDIM * IDIM;
    unsigned splitBlocks = (unsigned)(((W1 + WD) / 4 + 255) / 256);
    k_splitw<<<splitBlocks, 256>>>(wg, wu, wd);

    k_gather<<<NPAIR, 128>>>(x);

    dim3 g1(N2I / BN, MAXT);   // (22, 72)
    k_gemm<HDIM, false><<<g1, 256, SMEM_TOTAL>>>();

    size_t actN = (size_t)NPAIR * IDIM / 4;
    k_act<<<(unsigned)((actN + 255) / 256), 256>>>();

    dim3 g2(HDIM / BN, MAXT);  // (8, 72)
    k_gemm<IDIM, true><<<g2, 256, SMEM_TOTAL>>>();

    size_t redN = (size_t)T_TOK * HDIM / 4;
    k_reduce<<<(unsigned)((redN + 255) / 256), 256>>>(out);
}

// round 6
// speedup vs baseline: 4.2826x; 1.7473x over previous
#include <cuda_runtime.h>
#include <cuda_fp16.h>
#include <math.h>
#include <stdint.h>

#define T_TOK 4096
#define HDIM  1024
#define IDIM  1408
#define NEXP  8
#define NPAIR (T_TOK * 2)
#define N2I   (2 * IDIM)           // 2816 (interleaved gate/up rows)
#define BM 128
#define BN 128
#define BKH 64                     // K halves per stage (128B rows)
#define MAXT 72

// smem: rows 128B data + 16B pad = 144B (ldmatrix stride 36 words -> conflict-free)
#define ROWB 144
#define REG  (128 * ROWB)          // 18432 B per operand region
#define O_AH 0
#define O_BH (REG)
#define O_BL (2 * REG)
#define STAGEB (3 * REG)           // 55296
#define SMEM_TOTAL (2 * STAGEB)    // 110592 -> 2 CTAs/SM

// ---------------- scratch (static device globals; no allocations) ----------
__device__ int   g_count[NEXP];
__device__ int   g_list [NEXP * T_TOK];
__device__ float g_wt   [NEXP * T_TOK];
__device__ int   g_slot [NEXP * T_TOK];
__device__ int   g_base [NEXP];
__device__ int   g_tileE[MAXT];
__device__ int   g_tileRow[MAXT];
__device__ int   g_numTiles;

__device__ __half g_xh [(size_t)NPAIR * HDIM];
__device__ __half g_w1h[(size_t)NEXP * N2I * HDIM];   // interleaved: row 2i=gate_i, 2i+1=up_i
__device__ __half g_w1l[(size_t)NEXP * N2I * HDIM];
__device__ __half g_wdh[(size_t)NEXP * HDIM * IDIM];
__device__ __half g_wdl[(size_t)NEXP * HDIM * IDIM];
__device__ __half g_hh [(size_t)NPAIR * IDIM];
__device__ float  g_y  [(size_t)NPAIR * HDIM];

// ---------------- helpers -------------------------------------------------
__device__ __forceinline__ uint32_t smem_u32(const void* p) {
    uint32_t a;
    asm("{ .reg .u64 t; cvta.to.shared.u64 t, %1; cvt.u32.u64 %0, t; }" : "=r"(a) : "l"(p));
    return a;
}
__device__ __forceinline__ void cp16(uint32_t s, const void* g, bool v) {
    int sz = v ? 16 : 0;
    asm volatile("cp.async.cg.shared.global [%0], [%1], 16, %2;" :: "r"(s), "l"(g), "r"(sz) : "memory");
}
__device__ __forceinline__ void ldsm4(uint32_t* r, uint32_t addr) {
    asm volatile("ldmatrix.sync.aligned.m8n8.x4.shared.b16 {%0,%1,%2,%3}, [%4];"
                 : "=r"(r[0]), "=r"(r[1]), "=r"(r[2]), "=r"(r[3]) : "r"(addr));
}
__device__ __forceinline__ void mma16816(float* c, const uint32_t* a, uint32_t b0, uint32_t b1) {
    asm volatile("mma.sync.aligned.m16n8k16.row.col.f32.f16.f16.f32 "
                 "{%0,%1,%2,%3}, {%4,%5,%6,%7}, {%8,%9}, {%0,%1,%2,%3};"
                 : "+f"(c[0]), "+f"(c[1]), "+f"(c[2]), "+f"(c[3])
                 : "r"(a[0]), "r"(a[1]), "r"(a[2]), "r"(a[3]), "r"(b0), "r"(b1));
}
__device__ __forceinline__ void split_store(float4 v, __half* hp, __half* lp) {
    __half h0 = __float2half_rn(v.x), h1 = __float2half_rn(v.y);
    __half h2 = __float2half_rn(v.z), h3 = __float2half_rn(v.w);
    __half l0 = __float2half_rn(v.x - __half2float(h0));
    __half l1 = __float2half_rn(v.y - __half2float(h1));
    __half l2 = __float2half_rn(v.z - __half2float(h2));
    __half l3 = __float2half_rn(v.w - __half2float(h3));
    ((__half2*)hp)[0] = __halves2half2(h0, h1);
    ((__half2*)hp)[1] = __halves2half2(h2, h3);
    ((__half2*)lp)[0] = __halves2half2(l0, l1);
    ((__half2*)lp)[1] = __halves2half2(l2, l3);
}

// ---------------- init ----------------------------------------------------
__global__ void k_init() {
    if (threadIdx.x < NEXP) g_count[threadIdx.x] = 0;
}

// ---------------- router: one warp per token ------------------------------
__global__ void k_router(const float* __restrict__ x, const float* __restrict__ rw) {
    int warp = (blockIdx.x * blockDim.x + threadIdx.x) >> 5;
    int lane = threadIdx.x & 31;
    if (warp >= T_TOK) return;
    const float* xr = x + (size_t)warp * HDIM;

    float xv[32];
#pragma unroll
    for (int j = 0; j < 32; j++) xv[j] = xr[lane + j * 32];

    float logits[NEXP];
#pragma unroll
    for (int e = 0; e < NEXP; e++) {
        const float* wr = rw + (size_t)e * HDIM;
        float acc = 0.f;
#pragma unroll
        for (int j = 0; j < 32; j++) acc += xv[j] * wr[lane + j * 32];
#pragma unroll
        for (int s = 16; s > 0; s >>= 1) acc += __shfl_xor_sync(0xffffffffu, acc, s);
        logits[e] = acc;
    }

    if (lane == 0) {
        int e1 = 0;
#pragma unroll
        for (int e = 1; e < NEXP; e++) if (logits[e] > logits[e1]) e1 = e;
        int e2 = (e1 == 0) ? 1 : 0;
#pragma unroll
        for (int e = 0; e < NEXP; e++)
            if (e != e1 && logits[e] > logits[e2]) e2 = e;
        float t  = expf(logits[e2] - logits[e1]);
        float w1 = 1.f / (1.f + t);
        float w2 = t   / (1.f + t);

        int i1 = atomicAdd(&g_count[e1], 1);
        g_list[e1 * T_TOK + i1] = warp;
        g_wt  [e1 * T_TOK + i1] = w1;
        g_slot[e1 * T_TOK + i1] = 2 * warp + 0;

        int i2 = atomicAdd(&g_count[e2], 1);
        g_list[e2 * T_TOK + i2] = warp;
        g_wt  [e2 * T_TOK + i2] = w2;
        g_slot[e2 * T_TOK + i2] = 2 * warp + 1;
    }
}

// ---------------- tile table ---------------------------------------------
__global__ void k_build() {
    if (threadIdx.x != 0 || blockIdx.x != 0) return;
    int base = 0, nt = 0;
    for (int e = 0; e < NEXP; e++) {
        g_base[e] = base;
        int c = g_count[e];
        int tiles = (c + BM - 1) / BM;
        for (int r = 0; r < tiles; r++) {
            g_tileE[nt]   = e;
            g_tileRow[nt] = r * BM;
            nt++;
        }
        base += c;
    }
    g_numTiles = nt;
}

// ---------------- weight split: fp32 -> (hi,lo), interleave gate/up -------
__global__ void k_splitw(const float* __restrict__ wg, const float* __restrict__ wu,
                         const float* __restrict__ wd) {
    const size_t WG = (size_t)NEXP * IDIM * HDIM;   // 11,534,336
    const size_t WD = (size_t)NEXP * HDIM * IDIM;
    size_t idx4 = (size_t)blockIdx.x * blockDim.x + threadIdx.x;
    size_t f = idx4 * 4;
    if (f < WG) {                       // gate -> row 2i
        size_t e = f / ((size_t)IDIM * HDIM);
        size_t r = f % ((size_t)IDIM * HDIM);
        size_t i = r / HDIM, k = r % HDIM;
        float4 v = *(const float4*)(wg + f);
        size_t dst = ((size_t)e * N2I + 2 * i) * HDIM + k;
        split_store(v, g_w1h + dst, g_w1l + dst);
    } else if (f < 2 * WG) {            // up -> row 2i+1
        size_t f2 = f - WG;
        size_t e = f2 / ((size_t)IDIM * HDIM);
        size_t r = f2 % ((size_t)IDIM * HDIM);
        size_t i = r / HDIM, k = r % HDIM;
        float4 v = *(const float4*)(wu + f2);
        size_t dst = ((size_t)e * N2I + 2 * i + 1) * HDIM + k;
        split_store(v, g_w1h + dst, g_w1l + dst);
    } else if (f < 2 * WG + WD) {       // down, linear
        size_t f2 = f - 2 * WG;
        float4 v = *(const float4*)(wd + f2);
        split_store(v, g_wdh + f2, g_wdl + f2);
    }
}

// ---------------- gather: fp32 rows -> fp16 hi, sorted order --------------
__global__ void k_gather(const float* __restrict__ x) {
    int p = blockIdx.x;
    int e = 0;
#pragma unroll
    for (int i = 0; i < NEXP; i++)
        if (p >= g_base[i] && p < g_base[i] + g_count[i]) e = i;
    int r   = p - g_base[e];
    int tok = g_list[e * T_TOK + r];
    const float* src = x + (size_t)tok * HDIM;
    __half* dst = g_xh + (size_t)p * HDIM;
    for (int c = threadIdx.x * 4; c < HDIM; c += blockDim.x * 4) {
        float4 v = *(const float4*)(src + c);
        ((__half2*)(dst + c))[0] = __halves2half2(__float2half_rn(v.x), __float2half_rn(v.y));
        ((__half2*)(dst + c))[1] = __halves2half2(__float2half_rn(v.z), __float2half_rn(v.w));
    }
}

// ---------------- 2-term split HMMA GEMM ----------------------------------
// C = Ah @ (Bh + Bl)^T ; G1 fuses silu(gate)*up -> g_hh ; G2 scales+scatters
template <int KD, bool G2>
__global__ void __launch_bounds__(256, 2) k_gemm() {
    int tileIdx = blockIdx.y;
    if (tileIdx >= g_numTiles) return;
    extern __shared__ char smem[];
    uint32_t sb = smem_u32(smem);
    int tid  = threadIdx.x;
    int lane = tid & 31, wid = tid >> 5;
    int wm0 = (wid >> 1) * 32;
    int wn0 = (wid & 1) * 64;

    int e = g_tileE[tileIdx], row0 = g_tileRow[tileIdx];
    int cnt = g_count[e], base = g_base[e];
    int n0 = blockIdx.x * BN;
    int mrem = cnt - row0;

    const __half* aH = (G2 ? g_hh : g_xh) + (size_t)(base + row0) * KD;
    const int brows = G2 ? HDIM : N2I;
    const __half* bH = (G2 ? g_wdh : g_w1h) + ((size_t)e * brows + n0) * KD;
    const __half* bL = (G2 ? g_wdl : g_w1l) + ((size_t)e * brows + n0) * KD;

    // per stage: 3 regions x 128 rows x 8 chunks(16B) = 3072 chunks, 12/thread
    auto load_stage = [&](int buf, int k0) {
        uint32_t s0 = sb + buf * STAGEB;
#pragma unroll
        for (int i = 0; i < 4; i++) {
            int q = tid + i * 256;
            int row = q >> 3, c = q & 7;
            uint32_t so = row * ROWB + c * 16;
            size_t go = (size_t)row * KD + k0 + c * 8;
            bool v = row < mrem;
            cp16(s0 + O_AH + so, aH + go, v);
            cp16(s0 + O_BH + so, bH + go, true);
            cp16(s0 + O_BL + so, bL + go, true);
        }
        asm volatile("cp.async.commit_group;" ::: "memory");
    };

    float acc[2][8][4];
#pragma unroll
    for (int a = 0; a < 2; a++)
#pragma unroll
        for (int b = 0; b < 8; b++)
#pragma unroll
            for (int c = 0; c < 4; c++) acc[a][b][c] = 0.f;

    int lr = lane & 7, lt = lane >> 3;
    int rowoff  = lr + (lt & 1) * 8;
    int bytesel = (lt >> 1) * 16;

    const int STAGES = KD / BKH;
    load_stage(0, 0);
    for (int s = 0; s < STAGES; s++) {
        if (s + 1 < STAGES) {
            load_stage((s + 1) & 1, (s + 1) * BKH);
            asm volatile("cp.async.wait_group 1;" ::: "memory");
        } else {
            asm volatile("cp.async.wait_group 0;" ::: "memory");
        }
        __syncthreads();

        uint32_t s0 = sb + (s & 1) * STAGEB;
#pragma unroll
        for (int ks = 0; ks < 4; ks++) {
            uint32_t kb = ks * 32 + bytesel;
            uint32_t ah[2][4];
#pragma unroll
            for (int mt = 0; mt < 2; mt++)
                ldsm4(ah[mt], s0 + O_AH + (wm0 + mt * 16 + rowoff) * ROWB + kb);
#pragma unroll
            for (int ng = 0; ng < 4; ng++) {
                uint32_t rb = (wn0 + ng * 16 + rowoff) * ROWB + kb;
                uint32_t bh[4], bl[4];
                ldsm4(bh, s0 + O_BH + rb);
                ldsm4(bl, s0 + O_BL + rb);
#pragma unroll
                for (int mt = 0; mt < 2; mt++) {
                    float* c0 = acc[mt][ng * 2];
                    float* c1 = acc[mt][ng * 2 + 1];
                    mma16816(c0, ah[mt], bh[0], bh[2]);
                    mma16816(c1, ah[mt], bh[1], bh[3]);
                    mma16816(c0, ah[mt], bl[0], bl[2]);
                    mma16816(c1, ah[mt], bl[1], bl[3]);
                }
            }
        }
        __syncthreads();
    }

    // ---------------- epilogue ----------------
    if (G2) {
        int gcol = n0 + wn0 + (lane & 3) * 2;
#pragma unroll
        for (int mt = 0; mt < 2; mt++) {
#pragma unroll
            for (int half = 0; half < 2; half++) {
                int rloc = wm0 + mt * 16 + (lane >> 2) + half * 8;
                if (rloc >= mrem) continue;
                int gr = row0 + rloc;
                float wscale  = g_wt[e * T_TOK + gr];
                float* outp = g_y + (size_t)g_slot[e * T_TOK + gr] * HDIM + gcol;
#pragma unroll
                for (int nt = 0; nt < 8; nt++) {
                    float2 v;
                    v.x = acc[mt][nt][half * 2 + 0] * wscale;
                    v.y = acc[mt][nt][half * 2 + 1] * wscale;
                    *(float2*)(outp + nt * 8) = v;
                }
            }
        }
    } else {
        // interleaved cols: even=gate_i, odd=up_i ; pair index in I-space
        int pairBase = (n0 >> 1) + (wn0 >> 1) + (lane & 3);
#pragma unroll
        for (int mt = 0; mt < 2; mt++) {
#pragma unroll
            for (int half = 0; half < 2; half++) {
                int rloc = wm0 + mt * 16 + (lane >> 2) + half * 8;
                if (rloc >= mrem) continue;
                __half* dst = g_hh + (size_t)(base + row0 + rloc) * IDIM + pairBase;
#pragma unroll
                for (int nt = 0; nt < 8; nt++) {
                    float g = acc[mt][nt][half * 2 + 0];
                    float u = acc[mt][nt][half * 2 + 1];
                    float h = g / (1.f + expf(-g)) * u;
                    dst[nt * 4] = __float2half_rn(h);
                }
            }
        }
    }
}

// ---------------- reduce: out[t] = y[2t] + y[2t+1] ------------------------
__global__ void k_reduce(float* __restrict__ out) {
    size_t idx = (size_t)blockIdx.x * blockDim.x + threadIdx.x;
    size_t total = (size_t)T_TOK * HDIM / 4;
    if (idx >= total) return;
    size_t t = idx / (HDIM / 4);
    size_t c = idx % (HDIM / 4);
    const float4 a = *(const float4*)&g_y[(2 * t)     * HDIM + c * 4];
    const float4 b = *(const float4*)&g_y[(2 * t + 1) * HDIM + c * 4];
    float4 o = make_float4(a.x + b.x, a.y + b.y, a.z + b.z, a.w + b.w);
    *(float4*)&out[idx * 4] = o;
}

// ---------------- launch --------------------------------------------------
extern "C" void kernel_launch(void* const* d_in, const int* in_sizes, int n_in,
                              void* d_out, int out_size) {
    const float* x  = (const float*)d_in[0];
    const float* rw = (const float*)d_in[1];
    const float* wg = (const float*)d_in[2];
    const float* wu = (const float*)d_in[3];
    const float* wd = (const float*)d_in[4];
    float* out = (float*)d_out;

    cudaFuncSetAttribute(k_gemm<HDIM, false>,
                         cudaFuncAttributeMaxDynamicSharedMemorySize, SMEM_TOTAL);
    cudaFuncSetAttribute(k_gemm<IDIM, true>,
                         cudaFuncAttributeMaxDynamicSharedMemorySize, SMEM_TOTAL);

    k_init<<<1, 32>>>();
    k_router<<<T_TOK / 8, 256>>>(x, rw);
    k_build<<<1, 1>>>();

    const size_t WG = (size_t)NEXP * IDIM * HDIM;
    const size_t WD = (size_t)NEXP * HDIM * IDIM;
    unsigned splitBlocks = (unsigned)(((2 * WG + WD) / 4 + 255) / 256);
    k_splitw<<<splitBlocks, 256>>>(wg, wu, wd);

    k_gather<<<NPAIR, 128>>>(x);

    dim3 g1(N2I / BN, MAXT);   // (22, 72)
    k_gemm<HDIM, false><<<g1, 256, SMEM_TOTAL>>>();

    dim3 g2(HDIM / BN, MAXT);  // (8, 72)
    k_gemm<IDIM, true><<<g2, 256, SMEM_TOTAL>>>();

    size_t redN = (size_t)T_TOK * HDIM / 4;
    k_reduce<<<(unsigned)((redN + 255) / 256), 256>>>(out);
}